// round 1
// baseline (speedup 1.0000x reference)
#include <cuda_runtime.h>
#include <cuda_bf16.h>

#define RGRID 128
#define NSTEPS 128
#define NCH 28

__global__ void __launch_bounds__(128) octree_render_kernel(
    const float* __restrict__ rays_o,
    const float* __restrict__ rays_d,
    const float* __restrict__ grid,
    const float* __restrict__ scaling,
    const float* __restrict__ offset,
    float* __restrict__ out,
    int N)
{
    int i = blockIdx.x * blockDim.x + threadIdx.x;
    if (i >= N) return;

    float rox = rays_o[3*i+0], roy = rays_o[3*i+1], roz = rays_o[3*i+2];
    float rdx = rays_d[3*i+0], rdy = rays_d[3*i+1], rdz = rays_d[3*i+2];

    // unit direction
    float inv_n = rsqrtf(rdx*rdx + rdy*rdy + rdz*rdz);
    float ux = rdx*inv_n, uy = rdy*inv_n, uz = rdz*inv_n;

    float sx = scaling[0], sy = scaling[1], sz = scaling[2];
    float fx = offset[0],  fy = offset[1],  fz = offset[2];

    float ox = rox*sx + fx, oy = roy*sy + fy, oz = roz*sz + fz;
    float dx = ux*sx, dy = uy*sy, dz = uz*sz;

    float dlen = sqrtf(dx*dx + dy*dy + dz*dz);
    float delta_scale = 1.0f/dlen;

    float ivx = 1.0f/((fabsf(dx) > 1e-9f) ? dx : 1e-9f);
    float ivy = 1.0f/((fabsf(dy) > 1e-9f) ? dy : 1e-9f);
    float ivz = 1.0f/((fabsf(dz) > 1e-9f) ? dz : 1e-9f);

    float t1x = (0.0f - ox)*ivx, t2x = (1.0f - ox)*ivx;
    float t1y = (0.0f - oy)*ivy, t2y = (1.0f - oy)*ivy;
    float t1z = (0.0f - oz)*ivz, t2z = (1.0f - oz)*ivz;

    float tlo = fmaxf(fmaxf(fminf(t1x,t2x), fminf(t1y,t2y)), fminf(t1z,t2z));
    float thi = fminf(fminf(fmaxf(t1x,t2x), fmaxf(t1y,t2y)), fmaxf(t1z,t2z));
    float tmin = fmaxf(tlo, 0.0f);

    if (!(thi > tmin)) {
        // invalid ray: alpha==0 every step -> output = BG
        out[3*i+0] = 1.0f; out[3*i+1] = 1.0f; out[3*i+2] = 1.0f;
        return;
    }

    float dt   = (thi - tmin) * (1.0f/(float)NSTEPS);
    float dtds = dt * delta_scale;

    // SH degree-2 basis of the unit direction
    const float C0 = 0.28209479177387814f;
    const float C1 = 0.4886025119029199f;
    float b0 = C0;
    float b1 = -C1*uy;
    float b2 =  C1*uz;
    float b3 = -C1*ux;
    float b4 =  1.0925484305920792f*ux*uy;
    float b5 = -1.0925484305920792f*uy*uz;
    float b6 =  0.31539156525252005f*(2.0f*uz*uz - ux*ux - uy*uy);
    float b7 = -1.0925484305920792f*ux*uz;
    float b8 =  0.5462742152960396f*(ux*ux - uy*uy);

    float T = 1.0f, cr = 0.0f, cg = 0.0f, cb = 0.0f;

    const int SZc = NCH;
    const int SY  = RGRID*NCH;
    const int SX  = RGRID*RGRID*NCH;

    for (int s = 0; s < NSTEPS; ++s) {
        float t  = tmin + ((float)s + 0.5f)*dt;
        float px = fmaf(t, dx, ox)*(float)RGRID - 0.5f;
        float py = fmaf(t, dy, oy)*(float)RGRID - 0.5f;
        float pz = fmaf(t, dz, oz)*(float)RGRID - 0.5f;
        px = fminf(fmaxf(px, 0.0f), 126.9999f);
        py = fminf(fmaxf(py, 0.0f), 126.9999f);
        pz = fminf(fmaxf(pz, 0.0f), 126.9999f);

        float gx = floorf(px), gy = floorf(py), gz = floorf(pz);
        int ix = (int)gx, iy = (int)gy, iz = (int)gz;
        float wx = px - gx, wy = py - gy, wz = pz - gz;
        float axw = 1.0f - wx, ayw = 1.0f - wy, azw = 1.0f - wz;

        int base = ((ix*RGRID + iy)*RGRID + iz)*NCH;

        int off[8];
        off[0] = base;             off[1] = base + SZc;
        off[2] = base + SY;        off[3] = base + SY + SZc;
        off[4] = base + SX;        off[5] = base + SX + SZc;
        off[6] = base + SX + SY;   off[7] = base + SX + SY + SZc;

        float w[8];
        w[0] = axw*ayw*azw; w[1] = axw*ayw*wz;
        w[2] = axw*wy*azw;  w[3] = axw*wy*wz;
        w[4] = wx*ayw*azw;  w[5] = wx*ayw*wz;
        w[6] = wx*wy*azw;   w[7] = wx*wy*wz;

        // ---- sigma pre-pass: trilerp channel 27 only ----
        float sg = 0.0f;
        #pragma unroll
        for (int c = 0; c < 8; ++c)
            sg = fmaf(w[c], __ldg(grid + off[c] + (NCH-1)), sg);

        // relu(trilerp) <= 0  -> alpha == 0 exactly -> nothing changes this step
        if (sg > 0.0f) {
            // ---- color path: dot basis with each corner's coeffs, trilerp the dots ----
            float a0 = 0.0f, a1 = 0.0f, a2 = 0.0f;
            #pragma unroll
            for (int c = 0; c < 8; ++c) {
                const float4* p = reinterpret_cast<const float4*>(grid + off[c]);
                float4 v0 = __ldg(p+0);
                float4 v1 = __ldg(p+1);
                float4 v2 = __ldg(p+2);
                float4 v3 = __ldg(p+3);
                float4 v4 = __ldg(p+4);
                float4 v5 = __ldg(p+5);
                float4 v6 = __ldg(p+6);
                // channel 0: coeffs vals[0..8]
                float d0 = b0*v0.x + b1*v0.y + b2*v0.z + b3*v0.w
                         + b4*v1.x + b5*v1.y + b6*v1.z + b7*v1.w + b8*v2.x;
                // channel 1: coeffs vals[9..17]
                float d1 = b0*v2.y + b1*v2.z + b2*v2.w
                         + b3*v3.x + b4*v3.y + b5*v3.z + b6*v3.w
                         + b7*v4.x + b8*v4.y;
                // channel 2: coeffs vals[18..26]
                float d2 = b0*v4.z + b1*v4.w
                         + b2*v5.x + b3*v5.y + b4*v5.z + b5*v5.w
                         + b6*v6.x + b7*v6.y + b8*v6.z;
                a0 = fmaf(w[c], d0, a0);
                a1 = fmaf(w[c], d1, a1);
                a2 = fmaf(w[c], d2, a2);
            }

            float alpha = 1.0f - __expf(-sg*dtds);
            float s0 = 1.0f/(1.0f + __expf(-a0));
            float s1 = 1.0f/(1.0f + __expf(-a1));
            float s2 = 1.0f/(1.0f + __expf(-a2));

            float Ta = T*alpha;
            cr = fmaf(Ta, s0, cr);
            cg = fmaf(Ta, s1, cg);
            cb = fmaf(Ta, s2, cb);
            T  = T*(1.0f - alpha);
            if (T < 1e-4f) break;   // remaining contribution bounded by 1e-4 absolute
        }
    }

    // rgb + T*BG  (BG = 1.0)
    out[3*i+0] = fmaf(T, 1.0f, cr);
    out[3*i+1] = fmaf(T, 1.0f, cg);
    out[3*i+2] = fmaf(T, 1.0f, cb);
}

extern "C" void kernel_launch(void* const* d_in, const int* in_sizes, int n_in,
                              void* d_out, int out_size) {
    const float* rays_o  = (const float*)d_in[0];
    const float* rays_d  = (const float*)d_in[1];
    const float* grid    = (const float*)d_in[2];
    const float* scaling = (const float*)d_in[3];
    const float* offset  = (const float*)d_in[4];
    float* out = (float*)d_out;

    int N = in_sizes[0] / 3;
    int threads = 128;
    int blocks = (N + threads - 1) / threads;
    octree_render_kernel<<<blocks, threads>>>(rays_o, rays_d, grid, scaling, offset, out, N);
}

// round 2
// speedup vs baseline: 1.5139x; 1.5139x over previous
#include <cuda_runtime.h>
#include <cuda_bf16.h>

#define RGRID 128
#define NSTEPS 128
#define NCH 28

__device__ __forceinline__ float gsum8(float v, unsigned m) {
    v += __shfl_xor_sync(m, v, 1);
    v += __shfl_xor_sync(m, v, 2);
    v += __shfl_xor_sync(m, v, 4);
    return v;
}

__global__ void __launch_bounds__(256, 4) octree_render_kernel(
    const float* __restrict__ rays_o,
    const float* __restrict__ rays_d,
    const float* __restrict__ grid,
    const float* __restrict__ scaling,
    const float* __restrict__ offset,
    float* __restrict__ out,
    int N)
{
    int tid  = blockIdx.x * blockDim.x + threadIdx.x;
    int ray  = tid >> 3;          // 8 lanes per ray
    int c    = tid & 7;           // corner id: bit2=dx, bit1=dy, bit0=dz
    if (ray >= N) return;

    int lane = threadIdx.x & 31;
    unsigned gmask = 0xFFu << (lane & 24);   // this group's 8-lane mask

    float rox = rays_o[3*ray+0], roy = rays_o[3*ray+1], roz = rays_o[3*ray+2];
    float rdx = rays_d[3*ray+0], rdy = rays_d[3*ray+1], rdz = rays_d[3*ray+2];

    float inv_n = rsqrtf(rdx*rdx + rdy*rdy + rdz*rdz);
    float ux = rdx*inv_n, uy = rdy*inv_n, uz = rdz*inv_n;

    float sx = scaling[0], sy = scaling[1], sz = scaling[2];
    float fx = offset[0],  fy = offset[1],  fz = offset[2];

    float ox = rox*sx + fx, oy = roy*sy + fy, oz = roz*sz + fz;
    float dx = ux*sx, dy = uy*sy, dz = uz*sz;

    float dlen = sqrtf(dx*dx + dy*dy + dz*dz);
    float delta_scale = 1.0f/dlen;

    float ivx = 1.0f/((fabsf(dx) > 1e-9f) ? dx : 1e-9f);
    float ivy = 1.0f/((fabsf(dy) > 1e-9f) ? dy : 1e-9f);
    float ivz = 1.0f/((fabsf(dz) > 1e-9f) ? dz : 1e-9f);

    float t1x = (0.0f - ox)*ivx, t2x = (1.0f - ox)*ivx;
    float t1y = (0.0f - oy)*ivy, t2y = (1.0f - oy)*ivy;
    float t1z = (0.0f - oz)*ivz, t2z = (1.0f - oz)*ivz;

    float tlo = fmaxf(fmaxf(fminf(t1x,t2x), fminf(t1y,t2y)), fminf(t1z,t2z));
    float thi = fminf(fminf(fmaxf(t1x,t2x), fmaxf(t1y,t2y)), fmaxf(t1z,t2z));
    float tmin = fmaxf(tlo, 0.0f);

    bool alive = (thi > tmin);
    float dt   = alive ? (thi - tmin) * (1.0f/(float)NSTEPS) : 0.0f;
    float dtds = dt * delta_scale;

    // SH degree-2 basis
    const float C0 = 0.28209479177387814f;
    const float C1 = 0.4886025119029199f;
    float b0 = C0;
    float b1 = -C1*uy;
    float b2 =  C1*uz;
    float b3 = -C1*ux;
    float b4 =  1.0925484305920792f*ux*uy;
    float b5 = -1.0925484305920792f*uy*uz;
    float b6 =  0.31539156525252005f*(2.0f*uz*uz - ux*ux - uy*uy);
    float b7 = -1.0925484305920792f*ux*uz;
    float b8 =  0.5462742152960396f*(ux*ux - uy*uy);

    float T = 1.0f, cr = 0.0f, cg = 0.0f, cb = 0.0f;

    const int SY = RGRID*NCH;
    const int SX = RGRID*RGRID*NCH;
    int cx = (c >> 2) & 1, cy = (c >> 1) & 1, cz = c & 1;
    int coff = cx*SX + cy*SY + cz*NCH;

    for (int s = 0; s < NSTEPS; ++s) {
        if (alive) {
            float t  = tmin + ((float)s + 0.5f)*dt;
            float px = fmaf(t, dx, ox)*(float)RGRID - 0.5f;
            float py = fmaf(t, dy, oy)*(float)RGRID - 0.5f;
            float pz = fmaf(t, dz, oz)*(float)RGRID - 0.5f;
            px = fminf(fmaxf(px, 0.0f), 126.9999f);
            py = fminf(fmaxf(py, 0.0f), 126.9999f);
            pz = fminf(fmaxf(pz, 0.0f), 126.9999f);

            float gx = floorf(px), gy = floorf(py), gz = floorf(pz);
            int ix = (int)gx, iy = (int)gy, iz = (int)gz;
            float wxx = px - gx, wyy = py - gy, wzz = pz - gz;

            int base = ((ix*RGRID + iy)*RGRID + iz)*NCH + coff;

            float wc = (cx ? wxx : 1.0f - wxx)
                     * (cy ? wyy : 1.0f - wyy)
                     * (cz ? wzz : 1.0f - wzz);

            // sigma: each lane loads its corner's channel 27
            float sg = gsum8(wc * __ldg(grid + base + (NCH-1)), gmask);

            if (sg > 0.0f) {   // group-uniform
                const float4* p = reinterpret_cast<const float4*>(grid + base);
                float4 v0 = __ldg(p+0);
                float4 v1 = __ldg(p+1);
                float4 v2 = __ldg(p+2);
                float4 v3 = __ldg(p+3);
                float4 v4 = __ldg(p+4);
                float4 v5 = __ldg(p+5);
                float4 v6 = __ldg(p+6);

                float d0 = b0*v0.x + b1*v0.y + b2*v0.z + b3*v0.w
                         + b4*v1.x + b5*v1.y + b6*v1.z + b7*v1.w + b8*v2.x;
                float d1 = b0*v2.y + b1*v2.z + b2*v2.w
                         + b3*v3.x + b4*v3.y + b5*v3.z + b6*v3.w
                         + b7*v4.x + b8*v4.y;
                float d2 = b0*v4.z + b1*v4.w
                         + b2*v5.x + b3*v5.y + b4*v5.z + b5*v5.w
                         + b6*v6.x + b7*v6.y + b8*v6.z;

                float a0 = gsum8(wc * d0, gmask);
                float a1 = gsum8(wc * d1, gmask);
                float a2 = gsum8(wc * d2, gmask);

                float alpha = 1.0f - __expf(-sg*dtds);
                float s0 = 1.0f/(1.0f + __expf(-a0));
                float s1 = 1.0f/(1.0f + __expf(-a1));
                float s2 = 1.0f/(1.0f + __expf(-a2));

                float Ta = T*alpha;
                cr = fmaf(Ta, s0, cr);
                cg = fmaf(Ta, s1, cg);
                cb = fmaf(Ta, s2, cb);
                T  = T*(1.0f - alpha);
                if (T < 1e-4f) alive = false;   // bounded 1e-4 abs error
            }
        }
    }

    if (c == 0) {
        out[3*ray+0] = fmaf(T, 1.0f, cr);
        out[3*ray+1] = fmaf(T, 1.0f, cg);
        out[3*ray+2] = fmaf(T, 1.0f, cb);
    }
}

extern "C" void kernel_launch(void* const* d_in, const int* in_sizes, int n_in,
                              void* d_out, int out_size) {
    const float* rays_o  = (const float*)d_in[0];
    const float* rays_d  = (const float*)d_in[1];
    const float* grid    = (const float*)d_in[2];
    const float* scaling = (const float*)d_in[3];
    const float* offset  = (const float*)d_in[4];
    float* out = (float*)d_out;

    int N = in_sizes[0] / 3;                 // rays
    int threads_total = N * 8;               // 8 lanes per ray
    int block = 256;
    int blocks = (threads_total + block - 1) / block;
    octree_render_kernel<<<blocks, block>>>(rays_o, rays_d, grid, scaling, offset, out, N);
}